// round 11
// baseline (speedup 1.0000x reference)
#include <cuda_runtime.h>
#include <cuda_fp16.h>
#include <math.h>
#include <stdint.h>

// ---------------------------------------------------------------------------
// ViT block, all matmul on mma.sync fp16 (fp32 accumulate).
// Four batch-quarters pipelined across origin + 3 created streams.
// GELU via normcdff (gelu(x) = x * Phi(x)); V-fragments via ldmatrix.x4.trans.
// ---------------------------------------------------------------------------

#define Bq   8
#define Nq   1024
#define Cq   1024
#define Mrows (Bq*Nq)          // 8192
#define NCHUNK 4
#define MCHUNK (Mrows/NCHUNK)  // 2048 rows (2 batches) per chain
#define EPSLN 1e-6f

// Scratch (static device memory)
__device__ __half g_xh  [Mrows * Cq];
__device__ __half g_qkvh[Mrows * 3 * Cq];
__device__ __half g_atth[Mrows * Cq];
__device__ float  g_a   [Mrows * Cq];
__device__ float  g_y1  [Mrows * Cq];
__device__ __half g_y1h [Mrows * Cq];
__device__ __half g_h1h [Mrows * 4 * Cq];
__device__ float  g_h2  [Mrows * Cq];
__device__ __half g_wqkvT[3 * Cq * Cq];
__device__ __half g_wprojT[Cq * Cq];
__device__ __half g_wfc1T[4 * Cq * Cq];
__device__ __half g_wfc2T[Cq * 4 * Cq];

__device__ __forceinline__ uint32_t smem_u32(const void* p) {
    uint32_t a;
    asm("{ .reg .u64 t; cvta.to.shared.u64 t, %1; cvt.u32.u64 %0, t; }" : "=r"(a) : "l"(p));
    return a;
}

#define MMA_F16(d, a, b)                                                   \
    asm volatile(                                                          \
        "mma.sync.aligned.m16n8k16.row.col.f32.f16.f16.f32 "               \
        "{%0,%1,%2,%3}, {%4,%5,%6,%7}, {%8,%9}, {%0,%1,%2,%3};"            \
        : "+f"(d[0]), "+f"(d[1]), "+f"(d[2]), "+f"(d[3])                   \
        : "r"(a[0]), "r"(a[1]), "r"(a[2]), "r"(a[3]), "r"(b[0]), "r"(b[1]))

#define LDSM_X4(r0, r1, r2, r3, addr)                                      \
    asm volatile("ldmatrix.sync.aligned.m8n8.x4.shared.b16 {%0,%1,%2,%3}, [%4];" \
                 : "=r"(r0), "=r"(r1), "=r"(r2), "=r"(r3) : "r"(addr))

#define LDSM_X4T(r0, r1, r2, r3, addr)                                     \
    asm volatile("ldmatrix.sync.aligned.m8n8.x4.trans.shared.b16 {%0,%1,%2,%3}, [%4];" \
                 : "=r"(r0), "=r"(r1), "=r"(r2), "=r"(r3) : "r"(addr))

#define CP_ASYNC16(dst, src) \
    asm volatile("cp.async.cg.shared.global [%0], [%1], 16;" :: "r"(dst), "l"(src))
#define CP_COMMIT() asm volatile("cp.async.commit_group;" ::: "memory")
#define CP_WAIT(n)  asm volatile("cp.async.wait_group %0;" :: "n"(n) : "memory")

extern __shared__ __align__(16) char g_dynsmem[];

// ---------------------------------------------------------------------------
// fp16 mma GEMM: C[M,N] = A[M,K] @ Bt[N,K]^T + bias (+GELU).
// 128x128 tile, BK=32, 4-stage cp.async, 256 threads (8 warps, 64x32 tiles).
// Fragments via ldmatrix.x4. Stage: A 128x40h + B 128x40h = 20480 B.
// ---------------------------------------------------------------------------
#define GEMM_SMEM 81920

__global__ __launch_bounds__(256, 2) void gemm_fp16(
    const __half* __restrict__ A, const __half* __restrict__ Bt,
    const float* __restrict__ bias, float* __restrict__ Cf,
    __half* __restrict__ Ch, int N, int K, int gelu)
{
    const uint32_t smu = smem_u32(g_dynsmem);

    const int tid  = threadIdx.x;
    const int lane = tid & 31;
    const int warp = tid >> 5;
    const int gid  = lane >> 2;
    const int tig  = lane & 3;
    const int wm   = (warp >> 2) * 64;
    const int wn   = (warp & 3) * 32;
    const int bm   = blockIdx.y * 128;
    const int bn   = blockIdx.x * 128;

    const int c1 = tid + 256;
    const int r0 = tid >> 2, q0c = (tid & 3);
    const int r1 = c1 >> 2,  q1c = (c1 & 3);

    const int lrowA = ((lane >> 3) & 1) * 8 + (lane & 7);
    const int lcolA = (lane >> 4) * 8;
    const int lrowB = ((lane >> 4) & 1) * 8 + (lane & 7);
    const int lcolB = ((lane >> 3) & 1) * 8;
    const uint32_t aoff = (uint32_t)(((wm + lrowA) * 40 + lcolA) * 2);
    const uint32_t boff = (uint32_t)(10240 + ((wn + lrowB) * 40 + lcolB) * 2);

    float acc[4][4][4];
#pragma unroll
    for (int mt = 0; mt < 4; mt++)
#pragma unroll
        for (int nt = 0; nt < 4; nt++)
#pragma unroll
            for (int r = 0; r < 4; r++) acc[mt][nt][r] = 0.f;

    const int T = K >> 5;

#define GEMM_ISSUE(t)                                                            \
    do {                                                                         \
        const uint32_t sb_ = smu + (uint32_t)(((t) & 3) * 20480);                \
        CP_ASYNC16(sb_ + r0 * 80 + q0c * 16, &A[(size_t)(bm + r0) * K + (t) * 32 + q0c * 8]); \
        CP_ASYNC16(sb_ + r1 * 80 + q1c * 16, &A[(size_t)(bm + r1) * K + (t) * 32 + q1c * 8]); \
        CP_ASYNC16(sb_ + 10240 + r0 * 80 + q0c * 16, &Bt[(size_t)(bn + r0) * K + (t) * 32 + q0c * 8]); \
        CP_ASYNC16(sb_ + 10240 + r1 * 80 + q1c * 16, &Bt[(size_t)(bn + r1) * K + (t) * 32 + q1c * 8]); \
        CP_COMMIT();                                                             \
    } while (0)

    GEMM_ISSUE(0); GEMM_ISSUE(1); GEMM_ISSUE(2);

    for (int t = 0; t < T; t++) {
        if (t < T - 2)      { CP_WAIT(2); }
        else if (t == T - 2){ CP_WAIT(1); }
        else                { CP_WAIT(0); }
        __syncthreads();
        if (t + 3 < T) GEMM_ISSUE(t + 3);

        const uint32_t sb = smu + (uint32_t)((t & 3) * 20480);
#pragma unroll
        for (int ks = 0; ks < 2; ks++) {
            uint32_t afr[4][4], bfr[4][2];
#pragma unroll
            for (int mt = 0; mt < 4; mt++)
                LDSM_X4(afr[mt][0], afr[mt][1], afr[mt][2], afr[mt][3],
                        sb + aoff + (uint32_t)(mt * 1280 + ks * 32));
#pragma unroll
            for (int ntp = 0; ntp < 2; ntp++)
                LDSM_X4(bfr[2 * ntp][0], bfr[2 * ntp][1],
                        bfr[2 * ntp + 1][0], bfr[2 * ntp + 1][1],
                        sb + boff + (uint32_t)(ntp * 1280 + ks * 32));
#pragma unroll
            for (int mt = 0; mt < 4; mt++)
#pragma unroll
                for (int nt = 0; nt < 4; nt++)
                    MMA_F16(acc[mt][nt], afr[mt], bfr[nt]);
        }
    }
#undef GEMM_ISSUE

#pragma unroll
    for (int mt = 0; mt < 4; mt++) {
        const int row0 = bm + wm + mt * 16 + gid;
#pragma unroll
        for (int nt = 0; nt < 4; nt++) {
            const int col = bn + wn + nt * 8 + tig * 2;
            float2 bv = *(const float2*)&bias[col];
            float c0 = acc[mt][nt][0] + bv.x;
            float c1 = acc[mt][nt][1] + bv.y;
            float c2 = acc[mt][nt][2] + bv.x;
            float c3 = acc[mt][nt][3] + bv.y;
            if (gelu) {
                // gelu(x) = x * Phi(x); Phi = standard normal CDF (exact erf form)
                c0 = c0 * normcdff(c0);
                c1 = c1 * normcdff(c1);
                c2 = c2 * normcdff(c2);
                c3 = c3 * normcdff(c3);
            }
            if (Cf) {
                float2 o01; o01.x = c0; o01.y = c1;
                float2 o23; o23.x = c2; o23.y = c3;
                *(float2*)&Cf[(size_t)row0 * N + col] = o01;
                *(float2*)&Cf[(size_t)(row0 + 8) * N + col] = o23;
            }
            if (Ch) {
                *(__half2*)&Ch[(size_t)row0 * N + col] = __floats2half2_rn(c0, c1);
                *(__half2*)&Ch[(size_t)(row0 + 8) * N + col] = __floats2half2_rn(c2, c3);
            }
        }
    }
}

// ---------------------------------------------------------------------------
// Flash attention, fp16 mma, cp.async double-buffered K/V, ldmatrix frags.
// grid (Nq/64, nbatch*H), 128 threads (4 warps, 16 q-rows each).
// ---------------------------------------------------------------------------
#define AS_H 72
#define ATTN_SMEM (5 * 64 * AS_H * 2)

__global__ __launch_bounds__(128, 4) void attn_fp16(
    const __half* __restrict__ qkv, __half* __restrict__ out)
{
    __half* Qs = (__half*)g_dynsmem;
    const uint32_t qbase = smem_u32(Qs);
    const uint32_t kbase0 = qbase + 64 * AS_H * 2;
    const uint32_t vbase0 = qbase + 3 * 64 * AS_H * 2;

    const int bh = blockIdx.y;
    const int b = bh >> 4;
    const int h = bh & 15;
    const int q0 = blockIdx.x * 64;
    const int tid = threadIdx.x;
    const int wid = tid >> 5;
    const int lane = tid & 31;
    const int gid = lane >> 2;
    const int tig = lane & 3;
    const int row0 = wid * 16 + gid;

    const size_t base = (size_t)b * Nq * (3 * Cq);
    const __half2 sc2 = __float2half2_rn(0.125f);

    const int lrowA = ((lane >> 3) & 1) * 8 + (lane & 7);
    const int lcolA = (lane >> 4) * 8;
    const int lrowB = ((lane >> 4) & 1) * 8 + (lane & 7);
    const int lcolB = ((lane >> 3) & 1) * 8;
    const uint32_t qoff = (uint32_t)(((wid * 16 + lrowA) * AS_H + lcolA) * 2);
    const uint32_t koff = (uint32_t)((lrowB * AS_H + lcolB) * 2);
    // V x4.trans lane mapping: lanes 0-7 rows k0-7 @ col nt, 8-15 rows k8-15 @ nt,
    // 16-23 rows k0-7 @ nt+8, 24-31 rows k8-15 @ nt+8
    const int vrow = ((lane >> 3) & 1) * 8 + (lane & 7);
    const int vcol = (lane >> 4) * 8;
    const uint32_t voff = (uint32_t)((vrow * AS_H + vcol) * 2);

    const int cr = tid >> 3;
    const int cc8 = tid & 7;

#pragma unroll
    for (int i = 0; i < 4; i++) {
        int idx = tid + i * 128;
        int r = idx >> 3;
        int c8 = idx & 7;
        uint4 v = *(const uint4*)&qkv[base + (size_t)(q0 + r) * (3 * Cq) + h * 64 + c8 * 8];
        __half2* hv = (__half2*)&v;
        hv[0] = __hmul2(hv[0], sc2);
        hv[1] = __hmul2(hv[1], sc2);
        hv[2] = __hmul2(hv[2], sc2);
        hv[3] = __hmul2(hv[3], sc2);
        *(uint4*)&Qs[r * AS_H + c8 * 8] = v;
    }

#define ATTN_ISSUE(t)                                                            \
    do {                                                                         \
        const uint32_t kb_ = kbase0 + (uint32_t)(((t) & 1) * 64 * AS_H * 2);     \
        const uint32_t vb_ = vbase0 + (uint32_t)(((t) & 1) * 64 * AS_H * 2);     \
        _Pragma("unroll")                                                        \
        for (int i_ = 0; i_ < 4; i_++) {                                         \
            const int r_ = cr + i_ * 16;                                         \
            const size_t src_ = base + (size_t)((t) * 64 + r_) * (3 * Cq) + h * 64 + cc8 * 8; \
            CP_ASYNC16(kb_ + (r_ * AS_H + cc8 * 8) * 2, &qkv[src_ + Cq]);        \
            CP_ASYNC16(vb_ + (r_ * AS_H + cc8 * 8) * 2, &qkv[src_ + 2 * Cq]);    \
        }                                                                        \
        CP_COMMIT();                                                             \
    } while (0)

    ATTN_ISSUE(0);
    __syncthreads();

    uint32_t qf[4][4];
#pragma unroll
    for (int ks = 0; ks < 4; ks++)
        LDSM_X4(qf[ks][0], qf[ks][1], qf[ks][2], qf[ks][3], qbase + qoff + ks * 32);

    float of[8][4];
#pragma unroll
    for (int nt = 0; nt < 8; nt++)
#pragma unroll
        for (int r = 0; r < 4; r++) of[nt][r] = 0.f;
    float m0 = -INFINITY, m1 = -INFINITY, l0 = 0.f, l1 = 0.f;

    const int TT = Nq / 64;
    for (int t = 0; t < TT; t++) {
        CP_WAIT(0);
        __syncthreads();
        if (t + 1 < TT) ATTN_ISSUE(t + 1);

        const uint32_t kb = kbase0 + (uint32_t)((t & 1) * 64 * AS_H * 2);
        const uint32_t vb = vbase0 + (uint32_t)((t & 1) * 64 * AS_H * 2);

        float sf[8][4];
#pragma unroll
        for (int nt = 0; nt < 8; nt++)
#pragma unroll
            for (int r = 0; r < 4; r++) sf[nt][r] = 0.f;
#pragma unroll
        for (int ks = 0; ks < 4; ks++) {
#pragma unroll
            for (int ntp = 0; ntp < 4; ntp++) {
                uint32_t b0, b1, b2, b3;
                LDSM_X4(b0, b1, b2, b3, kb + koff + (uint32_t)(ntp * 16 * AS_H * 2 + ks * 32));
                uint32_t f0[2] = {b0, b1};
                uint32_t f1[2] = {b2, b3};
                MMA_F16(sf[2 * ntp], qf[ks], f0);
                MMA_F16(sf[2 * ntp + 1], qf[ks], f1);
            }
        }

        float mx0 = -INFINITY, mx1 = -INFINITY;
#pragma unroll
        for (int nt = 0; nt < 8; nt++) {
            mx0 = fmaxf(mx0, fmaxf(sf[nt][0], sf[nt][1]));
            mx1 = fmaxf(mx1, fmaxf(sf[nt][2], sf[nt][3]));
        }
        mx0 = fmaxf(mx0, __shfl_xor_sync(0xffffffffu, mx0, 1));
        mx0 = fmaxf(mx0, __shfl_xor_sync(0xffffffffu, mx0, 2));
        mx1 = fmaxf(mx1, __shfl_xor_sync(0xffffffffu, mx1, 1));
        mx1 = fmaxf(mx1, __shfl_xor_sync(0xffffffffu, mx1, 2));
        const float mn0 = fmaxf(m0, mx0);
        const float mn1 = fmaxf(m1, mx1);
        const float cr0 = __expf(m0 - mn0);
        const float cr1 = __expf(m1 - mn1);
        float rs0 = 0.f, rs1 = 0.f;
#pragma unroll
        for (int nt = 0; nt < 8; nt++) {
            float p0 = __expf(sf[nt][0] - mn0);
            float p1 = __expf(sf[nt][1] - mn0);
            float p2 = __expf(sf[nt][2] - mn1);
            float p3 = __expf(sf[nt][3] - mn1);
            rs0 += p0 + p1;
            rs1 += p2 + p3;
            *(__half2*)&Qs[row0 * AS_H + nt * 8 + tig * 2] = __floats2half2_rn(p0, p1);
            *(__half2*)&Qs[(row0 + 8) * AS_H + nt * 8 + tig * 2] = __floats2half2_rn(p2, p3);
            of[nt][0] *= cr0; of[nt][1] *= cr0;
            of[nt][2] *= cr1; of[nt][3] *= cr1;
        }
        rs0 += __shfl_xor_sync(0xffffffffu, rs0, 1);
        rs0 += __shfl_xor_sync(0xffffffffu, rs0, 2);
        rs1 += __shfl_xor_sync(0xffffffffu, rs1, 1);
        rs1 += __shfl_xor_sync(0xffffffffu, rs1, 2);
        m0 = mn0; m1 = mn1;
        l0 = l0 * cr0 + rs0;
        l1 = l1 * cr1 + rs1;
        __syncwarp();

        // O += P @ V : 4 key-steps x 4 d-tile-pairs; P via x4, V via x4.trans
#pragma unroll
        for (int ks = 0; ks < 4; ks++) {
            uint32_t pf[4];
            LDSM_X4(pf[0], pf[1], pf[2], pf[3], qbase + qoff + (uint32_t)(ks * 32));
#pragma unroll
            for (int ntp = 0; ntp < 4; ntp++) {
                uint32_t b0, b1, b2, b3;
                LDSM_X4T(b0, b1, b2, b3,
                         vb + voff + (uint32_t)((ks * 16 * AS_H + ntp * 16) * 2));
                uint32_t f0[2] = {b0, b1};
                uint32_t f1[2] = {b2, b3};
                MMA_F16(of[2 * ntp], pf, f0);
                MMA_F16(of[2 * ntp + 1], pf, f1);
            }
        }
        __syncwarp();
    }
#undef ATTN_ISSUE

    const float inv0 = 1.f / l0;
    const float inv1 = 1.f / l1;
    const size_t grow0 = (size_t)b * Nq + q0 + row0;
#pragma unroll
    for (int nt = 0; nt < 8; nt++) {
        const int col = h * 64 + nt * 8 + tig * 2;
        *(__half2*)&out[grow0 * Cq + col] =
            __floats2half2_rn(of[nt][0] * inv0, of[nt][1] * inv0);
        *(__half2*)&out[(grow0 + 8) * Cq + col] =
            __floats2half2_rn(of[nt][2] * inv1, of[nt][3] * inv1);
    }
}

// ---------------------------------------------------------------------------
// fp32 -> half copy (8 elems/thread)
// ---------------------------------------------------------------------------
__global__ __launch_bounds__(256) void to_half(
    const float* __restrict__ in, __half* __restrict__ out)
{
    const size_t i = ((size_t)blockIdx.x * 256 + threadIdx.x) * 8;
    float4 v0 = *(const float4*)&in[i];
    float4 v1 = *(const float4*)&in[i + 4];
    uint4 o;
    *(__half2*)&o.x = __floats2half2_rn(v0.x, v0.y);
    *(__half2*)&o.y = __floats2half2_rn(v0.z, v0.w);
    *(__half2*)&o.z = __floats2half2_rn(v1.x, v1.y);
    *(__half2*)&o.w = __floats2half2_rn(v1.z, v1.w);
    *(uint4*)&out[i] = o;
}

// ---------------------------------------------------------------------------
// transpose + fp16 convert: out[n][k] = half(in[k][n])
// ---------------------------------------------------------------------------
__global__ __launch_bounds__(256) void transpose_half(
    const float* __restrict__ in, __half* __restrict__ out, int K, int N)
{
    __shared__ float t[32][33];
    const int n0 = blockIdx.x * 32, k0 = blockIdx.y * 32;
    const int tx = threadIdx.x, ty = threadIdx.y;
#pragma unroll
    for (int i = 0; i < 4; i++)
        t[ty + i * 8][tx] = in[(size_t)(k0 + ty + i * 8) * N + n0 + tx];
    __syncthreads();
#pragma unroll
    for (int i = 0; i < 4; i++)
        out[(size_t)(n0 + ty + i * 8) * K + k0 + tx] = __float2half_rn(t[tx][ty + i * 8]);
}

// ---------------------------------------------------------------------------
// out = res + LayerNorm(in)*g + b ; optional half copy of out
// ---------------------------------------------------------------------------
__global__ __launch_bounds__(256) void ln_add_kernel(
    const float* __restrict__ in, const float* __restrict__ res,
    const float* __restrict__ g, const float* __restrict__ bt,
    float* __restrict__ out, __half* __restrict__ outh)
{
    const int row = blockIdx.x;
    const int tid = threadIdx.x;
    const size_t off = (size_t)row * Cq + tid * 4;

    float4 v = *(const float4*)&in[off];
    float s = v.x + v.y + v.z + v.w;
    float ss = v.x * v.x + v.y * v.y + v.z * v.z + v.w * v.w;

#pragma unroll
    for (int o2 = 16; o2 > 0; o2 >>= 1) {
        s  += __shfl_xor_sync(0xffffffffu, s,  o2);
        ss += __shfl_xor_sync(0xffffffffu, ss, o2);
    }
    __shared__ float sh_s[8], sh_ss[8], red[2];
    if ((tid & 31) == 0) { sh_s[tid >> 5] = s; sh_ss[tid >> 5] = ss; }
    __syncthreads();
    if (tid < 32) {
        float a  = (tid < 8) ? sh_s[tid]  : 0.f;
        float a2 = (tid < 8) ? sh_ss[tid] : 0.f;
#pragma unroll
        for (int o2 = 4; o2 > 0; o2 >>= 1) {
            a  += __shfl_xor_sync(0xffffffffu, a,  o2);
            a2 += __shfl_xor_sync(0xffffffffu, a2, o2);
        }
        if (tid == 0) {
            float mean = a * (1.f / Cq);
            float var = a2 * (1.f / Cq) - mean * mean;
            red[0] = mean;
            red[1] = rsqrtf(var + EPSLN);
        }
    }
    __syncthreads();
    float mean = red[0], inv = red[1];

    float4 gv = *(const float4*)&g[tid * 4];
    float4 bv = *(const float4*)&bt[tid * 4];
    float4 rv = *(const float4*)&res[off];
    float4 o;
    o.x = rv.x + (v.x - mean) * inv * gv.x + bv.x;
    o.y = rv.y + (v.y - mean) * inv * gv.y + bv.y;
    o.z = rv.z + (v.z - mean) * inv * gv.z + bv.z;
    o.w = rv.w + (v.w - mean) * inv * gv.w + bv.w;
    *(float4*)&out[off] = o;
    if (outh) {
        uint2 ho;
        *(__half2*)&ho.x = __floats2half2_rn(o.x, o.y);
        *(__half2*)&ho.y = __floats2half2_rn(o.z, o.w);
        *(uint2*)&outh[off] = ho;
    }
}

// ---------------------------------------------------------------------------
// host launcher: 4 quarter-chains over origin + 3 streams
// ---------------------------------------------------------------------------
extern "C" void kernel_launch(void* const* d_in, const int* in_sizes, int n_in,
                              void* d_out, int out_size)
{
    const float* x      = (const float*)d_in[0];
    const float* qkv_w  = (const float*)d_in[1];
    const float* qkv_b  = (const float*)d_in[2];
    const float* proj_w = (const float*)d_in[3];
    const float* proj_b = (const float*)d_in[4];
    const float* n1_g   = (const float*)d_in[5];
    const float* n1_b   = (const float*)d_in[6];
    const float* fc1_w  = (const float*)d_in[7];
    const float* fc1_b  = (const float*)d_in[8];
    const float* fc2_w  = (const float*)d_in[9];
    const float* fc2_b  = (const float*)d_in[10];
    const float* n2_g   = (const float*)d_in[11];
    const float* n2_b   = (const float*)d_in[12];
    float* out = (float*)d_out;

    static __half *p_xh = nullptr, *p_qkvh, *p_atth, *p_y1h, *p_h1h,
                  *p_wqkv, *p_wproj, *p_wfc1, *p_wfc2;
    static float *p_a, *p_y1, *p_h2;
    static cudaStream_t sW, sA, sB;
    static cudaEvent_t evStart, evRoot, evX, evW, evA, evB, evC;
    if (!p_xh) {
        cudaGetSymbolAddress((void**)&p_xh,   g_xh);
        cudaGetSymbolAddress((void**)&p_qkvh, g_qkvh);
        cudaGetSymbolAddress((void**)&p_atth, g_atth);
        cudaGetSymbolAddress((void**)&p_a,    g_a);
        cudaGetSymbolAddress((void**)&p_y1,   g_y1);
        cudaGetSymbolAddress((void**)&p_y1h,  g_y1h);
        cudaGetSymbolAddress((void**)&p_h1h,  g_h1h);
        cudaGetSymbolAddress((void**)&p_h2,   g_h2);
        cudaGetSymbolAddress((void**)&p_wqkv, g_wqkvT);
        cudaGetSymbolAddress((void**)&p_wproj, g_wprojT);
        cudaGetSymbolAddress((void**)&p_wfc1, g_wfc1T);
        cudaGetSymbolAddress((void**)&p_wfc2, g_wfc2T);
        cudaFuncSetAttribute(gemm_fp16, cudaFuncAttributeMaxDynamicSharedMemorySize, GEMM_SMEM);
        cudaFuncSetAttribute(attn_fp16, cudaFuncAttributeMaxDynamicSharedMemorySize, ATTN_SMEM);
        cudaStreamCreateWithFlags(&sW, cudaStreamNonBlocking);
        cudaStreamCreateWithFlags(&sA, cudaStreamNonBlocking);
        cudaStreamCreateWithFlags(&sB, cudaStreamNonBlocking);
        cudaEventCreateWithFlags(&evStart, cudaEventDisableTiming);
        cudaEventCreateWithFlags(&evRoot, cudaEventDisableTiming);
        cudaEventCreateWithFlags(&evX, cudaEventDisableTiming);
        cudaEventCreateWithFlags(&evW, cudaEventDisableTiming);
        cudaEventCreateWithFlags(&evA, cudaEventDisableTiming);
        cudaEventCreateWithFlags(&evB, cudaEventDisableTiming);
        cudaEventCreateWithFlags(&evC, cudaEventDisableTiming);
    }

    // ---- fork ----
    cudaEventRecord(evStart, 0);
    cudaStreamWaitEvent(sW, evStart, 0);
    cudaStreamWaitEvent(sA, evStart, 0);
    cudaStreamWaitEvent(sB, evStart, 0);

    // sW: proj/fc1/fc2 weight transposes (then hosts quarter 3)
    transpose_half<<<dim3(Cq / 32, Cq / 32), dim3(32, 8), 0, sW>>>(proj_w, p_wproj, Cq, Cq);
    transpose_half<<<dim3(4 * Cq / 32, Cq / 32), dim3(32, 8), 0, sW>>>(fc1_w, p_wfc1, Cq, 4 * Cq);
    transpose_half<<<dim3(Cq / 32, 4 * Cq / 32), dim3(32, 8), 0, sW>>>(fc2_w, p_wfc2, 4 * Cq, Cq);
    cudaEventRecord(evW, sW);

    // sA: x -> half (then hosts quarter 1)
    to_half<<<Mrows * Cq / 2048, 256, 0, sA>>>(x, p_xh);
    cudaEventRecord(evX, sA);

    // origin: qkv_w transpose (then hosts quarter 0)
    transpose_half<<<dim3(3 * Cq / 32, Cq / 32), dim3(32, 8)>>>(qkv_w, p_wqkv, Cq, 3 * Cq);
    cudaEventRecord(evRoot, 0);

    // chain streams: q0=origin, q1=sA, q2=sB, q3=sW
    cudaStream_t chain[NCHUNK] = {(cudaStream_t)0, sA, sB, sW};

    cudaStreamWaitEvent(0, evX, 0);            // q0 needs x->half (qkv_w local)
    cudaStreamWaitEvent(sA, evRoot, 0);        // q1 needs qkv_w (x->half local)
    cudaStreamWaitEvent(sB, evRoot, 0);        // q2 needs both
    cudaStreamWaitEvent(sB, evX, 0);
    cudaStreamWaitEvent(sW, evRoot, 0);        // q3 needs both (transposes local)
    cudaStreamWaitEvent(sW, evX, 0);

    for (int q = 0; q < NCHUNK; q++) {
        cudaStream_t st = chain[q];
        const size_t m = (size_t)q * MCHUNK;
        const __half* xh  = p_xh  + m * Cq;
        __half* qkvh      = p_qkvh + m * 3 * Cq;
        __half* atth      = p_atth + m * Cq;
        float*  a_        = p_a    + m * Cq;
        float*  y1_       = p_y1   + m * Cq;
        __half* y1h_      = p_y1h  + m * Cq;
        __half* h1h_      = p_h1h  + m * 4 * Cq;
        float*  h2_       = p_h2   + m * Cq;
        float*  out_      = out    + m * Cq;

        // qkv
        gemm_fp16<<<dim3(3 * Cq / 128, MCHUNK / 128), 256, GEMM_SMEM, st>>>(
            xh, p_wqkv, qkv_b, nullptr, qkvh, 3 * Cq, Cq, 0);
        // attention (2 batches x 16 heads)
        attn_fp16<<<dim3(Nq / 64, (Bq / NCHUNK) * 16), 128, ATTN_SMEM, st>>>(qkvh, atth);
        // proj (needs transposed proj_w; q3 is on sW so already ordered)
        if (st != sW) cudaStreamWaitEvent(st, evW, 0);
        gemm_fp16<<<dim3(Cq / 128, MCHUNK / 128), 256, GEMM_SMEM, st>>>(
            atth, p_wproj, proj_b, a_, nullptr, Cq, Cq, 0);
        // y1 = a + LN(a)
        ln_add_kernel<<<MCHUNK, 256, 0, st>>>(a_, a_, n1_g, n1_b, y1_, y1h_);
        // fc1
        gemm_fp16<<<dim3(4 * Cq / 128, MCHUNK / 128), 256, GEMM_SMEM, st>>>(
            y1h_, p_wfc1, fc1_b, nullptr, h1h_, 4 * Cq, Cq, 1);
        // fc2
        gemm_fp16<<<dim3(Cq / 128, MCHUNK / 128), 256, GEMM_SMEM, st>>>(
            h1h_, p_wfc2, fc2_b, h2_, nullptr, Cq, 4 * Cq, 0);
        // out = y1 + LN(h2)
        ln_add_kernel<<<MCHUNK, 256, 0, st>>>(h2_, y1_, n2_g, n2_b, out_, nullptr);
    }

    // ---- join non-origin chains back to origin ----
    cudaEventRecord(evA, sA);
    cudaEventRecord(evB, sB);
    cudaEventRecord(evC, sW);
    cudaStreamWaitEvent(0, evA, 0);
    cudaStreamWaitEvent(0, evB, 0);
    cudaStreamWaitEvent(0, evC, 0);
}

// round 13
// speedup vs baseline: 1.0446x; 1.0446x over previous
#include <cuda_runtime.h>
#include <cuda_fp16.h>
#include <math.h>
#include <stdint.h>

// ---------------------------------------------------------------------------
// ViT block, all matmul on mma.sync fp16 (fp32 accumulate).
// Four batch-quarters pipelined across origin + 3 created streams (resource
// footprint identical to the proven round-8 config: 3 streams; 7 light events).
//   qkv = x @ qkv_w + qkv_b            (gemm_fp16 -> half)
//   flash-attention per (b,h)          (attn_fp16)
//   a  = att @ proj_w + proj_b         (gemm_fp16 -> fp32)
//   y1 = a + LN(a; n1)                 (ln_add -> fp32 + half)
//   h1 = GELU(y1 @ fc1_w + fc1_b)      (gemm_fp16 -> half, exact erff)
//   h2 = h1 @ fc2_w + fc2_b            (gemm_fp16 -> fp32)
//   out = y1 + LN(h2; n2)              (ln_add -> fp32)
// ---------------------------------------------------------------------------

#define Bq   8
#define Nq   1024
#define Cq   1024
#define Mrows (Bq*Nq)          // 8192
#define NCHUNK 4
#define MCHUNK (Mrows/NCHUNK)  // 2048 rows (2 batches) per chain
#define EPSLN 1e-6f

// Scratch (static device memory)
__device__ __half g_xh  [Mrows * Cq];
__device__ __half g_qkvh[Mrows * 3 * Cq];
__device__ __half g_atth[Mrows * Cq];
__device__ float  g_a   [Mrows * Cq];
__device__ float  g_y1  [Mrows * Cq];
__device__ __half g_y1h [Mrows * Cq];
__device__ __half g_h1h [Mrows * 4 * Cq];
__device__ float  g_h2  [Mrows * Cq];
__device__ __half g_wqkvT[3 * Cq * Cq];
__device__ __half g_wprojT[Cq * Cq];
__device__ __half g_wfc1T[4 * Cq * Cq];
__device__ __half g_wfc2T[Cq * 4 * Cq];

__device__ __forceinline__ uint32_t smem_u32(const void* p) {
    uint32_t a;
    asm("{ .reg .u64 t; cvta.to.shared.u64 t, %1; cvt.u32.u64 %0, t; }" : "=r"(a) : "l"(p));
    return a;
}

#define MMA_F16(d, a, b)                                                   \
    asm volatile(                                                          \
        "mma.sync.aligned.m16n8k16.row.col.f32.f16.f16.f32 "               \
        "{%0,%1,%2,%3}, {%4,%5,%6,%7}, {%8,%9}, {%0,%1,%2,%3};"            \
        : "+f"(d[0]), "+f"(d[1]), "+f"(d[2]), "+f"(d[3])                   \
        : "r"(a[0]), "r"(a[1]), "r"(a[2]), "r"(a[3]), "r"(b[0]), "r"(b[1]))

#define LDSM_X4(r0, r1, r2, r3, addr)                                      \
    asm volatile("ldmatrix.sync.aligned.m8n8.x4.shared.b16 {%0,%1,%2,%3}, [%4];" \
                 : "=r"(r0), "=r"(r1), "=r"(r2), "=r"(r3) : "r"(addr))

#define CP_ASYNC16(dst, src) \
    asm volatile("cp.async.cg.shared.global [%0], [%1], 16;" :: "r"(dst), "l"(src))
#define CP_COMMIT() asm volatile("cp.async.commit_group;" ::: "memory")
#define CP_WAIT(n)  asm volatile("cp.async.wait_group %0;" :: "n"(n) : "memory")

extern __shared__ __align__(16) char g_dynsmem[];

// ---------------------------------------------------------------------------
// fp16 mma GEMM: C[M,N] = A[M,K] @ Bt[N,K]^T + bias (+GELU).
// 128x128 tile, BK=32, 4-stage cp.async, 256 threads (8 warps, 64x32 tiles).
// Fragments via ldmatrix.x4. Stage: A 128x40h + B 128x40h = 20480 B.
// ---------------------------------------------------------------------------
#define GEMM_SMEM 81920

__global__ __launch_bounds__(256, 2) void gemm_fp16(
    const __half* __restrict__ A, const __half* __restrict__ Bt,
    const float* __restrict__ bias, float* __restrict__ Cf,
    __half* __restrict__ Ch, int N, int K, int gelu)
{
    const uint32_t smu = smem_u32(g_dynsmem);

    const int tid  = threadIdx.x;
    const int lane = tid & 31;
    const int warp = tid >> 5;
    const int gid  = lane >> 2;
    const int tig  = lane & 3;
    const int wm   = (warp >> 2) * 64;
    const int wn   = (warp & 3) * 32;
    const int bm   = blockIdx.y * 128;
    const int bn   = blockIdx.x * 128;

    const int c1 = tid + 256;
    const int r0 = tid >> 2, q0c = (tid & 3);
    const int r1 = c1 >> 2,  q1c = (c1 & 3);

    const int lrowA = ((lane >> 3) & 1) * 8 + (lane & 7);
    const int lcolA = (lane >> 4) * 8;
    const int lrowB = ((lane >> 4) & 1) * 8 + (lane & 7);
    const int lcolB = ((lane >> 3) & 1) * 8;
    const uint32_t aoff = (uint32_t)(((wm + lrowA) * 40 + lcolA) * 2);
    const uint32_t boff = (uint32_t)(10240 + ((wn + lrowB) * 40 + lcolB) * 2);

    float acc[4][4][4];
#pragma unroll
    for (int mt = 0; mt < 4; mt++)
#pragma unroll
        for (int nt = 0; nt < 4; nt++)
#pragma unroll
            for (int r = 0; r < 4; r++) acc[mt][nt][r] = 0.f;

    const int T = K >> 5;

#define GEMM_ISSUE(t)                                                            \
    do {                                                                         \
        const uint32_t sb_ = smu + (uint32_t)(((t) & 3) * 20480);                \
        CP_ASYNC16(sb_ + r0 * 80 + q0c * 16, &A[(size_t)(bm + r0) * K + (t) * 32 + q0c * 8]); \
        CP_ASYNC16(sb_ + r1 * 80 + q1c * 16, &A[(size_t)(bm + r1) * K + (t) * 32 + q1c * 8]); \
        CP_ASYNC16(sb_ + 10240 + r0 * 80 + q0c * 16, &Bt[(size_t)(bn + r0) * K + (t) * 32 + q0c * 8]); \
        CP_ASYNC16(sb_ + 10240 + r1 * 80 + q1c * 16, &Bt[(size_t)(bn + r1) * K + (t) * 32 + q1c * 8]); \
        CP_COMMIT();                                                             \
    } while (0)

    GEMM_ISSUE(0); GEMM_ISSUE(1); GEMM_ISSUE(2);

    for (int t = 0; t < T; t++) {
        if (t < T - 2)      { CP_WAIT(2); }
        else if (t == T - 2){ CP_WAIT(1); }
        else                { CP_WAIT(0); }
        __syncthreads();
        if (t + 3 < T) GEMM_ISSUE(t + 3);

        const uint32_t sb = smu + (uint32_t)((t & 3) * 20480);
#pragma unroll
        for (int ks = 0; ks < 2; ks++) {
            uint32_t afr[4][4], bfr[4][2];
#pragma unroll
            for (int mt = 0; mt < 4; mt++)
                LDSM_X4(afr[mt][0], afr[mt][1], afr[mt][2], afr[mt][3],
                        sb + aoff + (uint32_t)(mt * 1280 + ks * 32));
#pragma unroll
            for (int ntp = 0; ntp < 2; ntp++)
                LDSM_X4(bfr[2 * ntp][0], bfr[2 * ntp][1],
                        bfr[2 * ntp + 1][0], bfr[2 * ntp + 1][1],
                        sb + boff + (uint32_t)(ntp * 1280 + ks * 32));
#pragma unroll
            for (int mt = 0; mt < 4; mt++)
#pragma unroll
                for (int nt = 0; nt < 4; nt++)
                    MMA_F16(acc[mt][nt], afr[mt], bfr[nt]);
        }
    }
#undef GEMM_ISSUE

#pragma unroll
    for (int mt = 0; mt < 4; mt++) {
        const int row0 = bm + wm + mt * 16 + gid;
#pragma unroll
        for (int nt = 0; nt < 4; nt++) {
            const int col = bn + wn + nt * 8 + tig * 2;
            float2 bv = *(const float2*)&bias[col];
            float c0 = acc[mt][nt][0] + bv.x;
            float c1 = acc[mt][nt][1] + bv.y;
            float c2 = acc[mt][nt][2] + bv.x;
            float c3 = acc[mt][nt][3] + bv.y;
            if (gelu) {
                c0 = 0.5f * c0 * (1.f + erff(c0 * 0.70710678118654752f));
                c1 = 0.5f * c1 * (1.f + erff(c1 * 0.70710678118654752f));
                c2 = 0.5f * c2 * (1.f + erff(c2 * 0.70710678118654752f));
                c3 = 0.5f * c3 * (1.f + erff(c3 * 0.70710678118654752f));
            }
            if (Cf) {
                float2 o01; o01.x = c0; o01.y = c1;
                float2 o23; o23.x = c2; o23.y = c3;
                *(float2*)&Cf[(size_t)row0 * N + col] = o01;
                *(float2*)&Cf[(size_t)(row0 + 8) * N + col] = o23;
            }
            if (Ch) {
                *(__half2*)&Ch[(size_t)row0 * N + col] = __floats2half2_rn(c0, c1);
                *(__half2*)&Ch[(size_t)(row0 + 8) * N + col] = __floats2half2_rn(c2, c3);
            }
        }
    }
}

// ---------------------------------------------------------------------------
// Flash attention, fp16 mma, cp.async double-buffered K/V, ldmatrix frags.
// grid (Nq/64, nbatch*H), 128 threads (4 warps, 16 q-rows each).
// ---------------------------------------------------------------------------
#define AS_H 72
#define ATTN_SMEM (5 * 64 * AS_H * 2)

__global__ __launch_bounds__(128, 4) void attn_fp16(
    const __half* __restrict__ qkv, __half* __restrict__ out)
{
    __half* Qs = (__half*)g_dynsmem;
    const uint32_t qbase = smem_u32(Qs);
    const uint32_t kbase0 = qbase + 64 * AS_H * 2;
    const uint32_t vbase0 = qbase + 3 * 64 * AS_H * 2;

    const int bh = blockIdx.y;
    const int b = bh >> 4;
    const int h = bh & 15;
    const int q0 = blockIdx.x * 64;
    const int tid = threadIdx.x;
    const int wid = tid >> 5;
    const int lane = tid & 31;
    const int gid = lane >> 2;
    const int tig = lane & 3;
    const int row0 = wid * 16 + gid;

    const size_t base = (size_t)b * Nq * (3 * Cq);
    const __half2 sc2 = __float2half2_rn(0.125f);

    const int lrowA = ((lane >> 3) & 1) * 8 + (lane & 7);
    const int lcolA = (lane >> 4) * 8;
    const int lrowB = ((lane >> 4) & 1) * 8 + (lane & 7);
    const int lcolB = ((lane >> 3) & 1) * 8;
    const uint32_t qoff = (uint32_t)(((wid * 16 + lrowA) * AS_H + lcolA) * 2);
    const uint32_t koff = (uint32_t)((lrowB * AS_H + lcolB) * 2);

    const int cr = tid >> 3;
    const int cc8 = tid & 7;

#pragma unroll
    for (int i = 0; i < 4; i++) {
        int idx = tid + i * 128;
        int r = idx >> 3;
        int c8 = idx & 7;
        uint4 v = *(const uint4*)&qkv[base + (size_t)(q0 + r) * (3 * Cq) + h * 64 + c8 * 8];
        __half2* hv = (__half2*)&v;
        hv[0] = __hmul2(hv[0], sc2);
        hv[1] = __hmul2(hv[1], sc2);
        hv[2] = __hmul2(hv[2], sc2);
        hv[3] = __hmul2(hv[3], sc2);
        *(uint4*)&Qs[r * AS_H + c8 * 8] = v;
    }

#define ATTN_ISSUE(t)                                                            \
    do {                                                                         \
        const uint32_t kb_ = kbase0 + (uint32_t)(((t) & 1) * 64 * AS_H * 2);     \
        const uint32_t vb_ = vbase0 + (uint32_t)(((t) & 1) * 64 * AS_H * 2);     \
        _Pragma("unroll")                                                        \
        for (int i_ = 0; i_ < 4; i_++) {                                         \
            const int r_ = cr + i_ * 16;                                         \
            const size_t src_ = base + (size_t)((t) * 64 + r_) * (3 * Cq) + h * 64 + cc8 * 8; \
            CP_ASYNC16(kb_ + (r_ * AS_H + cc8 * 8) * 2, &qkv[src_ + Cq]);        \
            CP_ASYNC16(vb_ + (r_ * AS_H + cc8 * 8) * 2, &qkv[src_ + 2 * Cq]);    \
        }                                                                        \
        CP_COMMIT();                                                             \
    } while (0)

    ATTN_ISSUE(0);
    __syncthreads();

    uint32_t qf[4][4];
#pragma unroll
    for (int ks = 0; ks < 4; ks++)
        LDSM_X4(qf[ks][0], qf[ks][1], qf[ks][2], qf[ks][3], qbase + qoff + ks * 32);

    float of[8][4];
#pragma unroll
    for (int nt = 0; nt < 8; nt++)
#pragma unroll
        for (int r = 0; r < 4; r++) of[nt][r] = 0.f;
    float m0 = -INFINITY, m1 = -INFINITY, l0 = 0.f, l1 = 0.f;

    const int TT = Nq / 64;
    for (int t = 0; t < TT; t++) {
        CP_WAIT(0);
        __syncthreads();
        if (t + 1 < TT) ATTN_ISSUE(t + 1);

        const uint32_t kb = kbase0 + (uint32_t)((t & 1) * 64 * AS_H * 2);
        const uint32_t vb = vbase0 + (uint32_t)((t & 1) * 64 * AS_H * 2);

        float sf[8][4];
#pragma unroll
        for (int nt = 0; nt < 8; nt++)
#pragma unroll
            for (int r = 0; r < 4; r++) sf[nt][r] = 0.f;
#pragma unroll
        for (int ks = 0; ks < 4; ks++) {
#pragma unroll
            for (int ntp = 0; ntp < 4; ntp++) {
                uint32_t b0, b1, b2, b3;
                LDSM_X4(b0, b1, b2, b3, kb + koff + (uint32_t)(ntp * 16 * AS_H * 2 + ks * 32));
                uint32_t f0[2] = {b0, b1};
                uint32_t f1[2] = {b2, b3};
                MMA_F16(sf[2 * ntp], qf[ks], f0);
                MMA_F16(sf[2 * ntp + 1], qf[ks], f1);
            }
        }

        float mx0 = -INFINITY, mx1 = -INFINITY;
#pragma unroll
        for (int nt = 0; nt < 8; nt++) {
            mx0 = fmaxf(mx0, fmaxf(sf[nt][0], sf[nt][1]));
            mx1 = fmaxf(mx1, fmaxf(sf[nt][2], sf[nt][3]));
        }
        mx0 = fmaxf(mx0, __shfl_xor_sync(0xffffffffu, mx0, 1));
        mx0 = fmaxf(mx0, __shfl_xor_sync(0xffffffffu, mx0, 2));
        mx1 = fmaxf(mx1, __shfl_xor_sync(0xffffffffu, mx1, 1));
        mx1 = fmaxf(mx1, __shfl_xor_sync(0xffffffffu, mx1, 2));
        const float mn0 = fmaxf(m0, mx0);
        const float mn1 = fmaxf(m1, mx1);
        const float cr0 = __expf(m0 - mn0);
        const float cr1 = __expf(m1 - mn1);
        float rs0 = 0.f, rs1 = 0.f;
#pragma unroll
        for (int nt = 0; nt < 8; nt++) {
            float p0 = __expf(sf[nt][0] - mn0);
            float p1 = __expf(sf[nt][1] - mn0);
            float p2 = __expf(sf[nt][2] - mn1);
            float p3 = __expf(sf[nt][3] - mn1);
            rs0 += p0 + p1;
            rs1 += p2 + p3;
            *(__half2*)&Qs[row0 * AS_H + nt * 8 + tig * 2] = __floats2half2_rn(p0, p1);
            *(__half2*)&Qs[(row0 + 8) * AS_H + nt * 8 + tig * 2] = __floats2half2_rn(p2, p3);
            of[nt][0] *= cr0; of[nt][1] *= cr0;
            of[nt][2] *= cr1; of[nt][3] *= cr1;
        }
        rs0 += __shfl_xor_sync(0xffffffffu, rs0, 1);
        rs0 += __shfl_xor_sync(0xffffffffu, rs0, 2);
        rs1 += __shfl_xor_sync(0xffffffffu, rs1, 1);
        rs1 += __shfl_xor_sync(0xffffffffu, rs1, 2);
        m0 = mn0; m1 = mn1;
        l0 = l0 * cr0 + rs0;
        l1 = l1 * cr1 + rs1;
        __syncwarp();

        const int rl = lane & 15;
#pragma unroll
        for (int ks = 0; ks < 4; ks++) {
            uint32_t pf[4];
            LDSM_X4(pf[0], pf[1], pf[2], pf[3], qbase + qoff + (uint32_t)(ks * 32));
#pragma unroll
            for (int nt = 0; nt < 8; nt++) {
                uint32_t b0, b1;
                uint32_t addr = vb + (uint32_t)(((ks * 16 + rl) * AS_H + nt * 8) * 2);
                asm volatile(
                    "ldmatrix.sync.aligned.m8n8.x2.trans.shared.b16 {%0,%1}, [%2];"
                    : "=r"(b0), "=r"(b1) : "r"(addr));
                uint32_t bfr[2] = {b0, b1};
                MMA_F16(of[nt], pf, bfr);
            }
        }
        __syncwarp();
    }
#undef ATTN_ISSUE

    const float inv0 = 1.f / l0;
    const float inv1 = 1.f / l1;
    const size_t grow0 = (size_t)b * Nq + q0 + row0;
#pragma unroll
    for (int nt = 0; nt < 8; nt++) {
        const int col = h * 64 + nt * 8 + tig * 2;
        *(__half2*)&out[grow0 * Cq + col] =
            __floats2half2_rn(of[nt][0] * inv0, of[nt][1] * inv0);
        *(__half2*)&out[(grow0 + 8) * Cq + col] =
            __floats2half2_rn(of[nt][2] * inv1, of[nt][3] * inv1);
    }
}

// ---------------------------------------------------------------------------
// fp32 -> half copy (8 elems/thread)
// ---------------------------------------------------------------------------
__global__ __launch_bounds__(256) void to_half(
    const float* __restrict__ in, __half* __restrict__ out)
{
    const size_t i = ((size_t)blockIdx.x * 256 + threadIdx.x) * 8;
    float4 v0 = *(const float4*)&in[i];
    float4 v1 = *(const float4*)&in[i + 4];
    uint4 o;
    *(__half2*)&o.x = __floats2half2_rn(v0.x, v0.y);
    *(__half2*)&o.y = __floats2half2_rn(v0.z, v0.w);
    *(__half2*)&o.z = __floats2half2_rn(v1.x, v1.y);
    *(__half2*)&o.w = __floats2half2_rn(v1.z, v1.w);
    *(uint4*)&out[i] = o;
}

// ---------------------------------------------------------------------------
// transpose + fp16 convert: out[n][k] = half(in[k][n])
// ---------------------------------------------------------------------------
__global__ __launch_bounds__(256) void transpose_half(
    const float* __restrict__ in, __half* __restrict__ out, int K, int N)
{
    __shared__ float t[32][33];
    const int n0 = blockIdx.x * 32, k0 = blockIdx.y * 32;
    const int tx = threadIdx.x, ty = threadIdx.y;
#pragma unroll
    for (int i = 0; i < 4; i++)
        t[ty + i * 8][tx] = in[(size_t)(k0 + ty + i * 8) * N + n0 + tx];
    __syncthreads();
#pragma unroll
    for (int i = 0; i < 4; i++)
        out[(size_t)(n0 + ty + i * 8) * K + k0 + tx] = __float2half_rn(t[tx][ty + i * 8]);
}

// ---------------------------------------------------------------------------
// out = res + LayerNorm(in)*g + b ; optional half copy of out
// ---------------------------------------------------------------------------
__global__ __launch_bounds__(256) void ln_add_kernel(
    const float* __restrict__ in, const float* __restrict__ res,
    const float* __restrict__ g, const float* __restrict__ bt,
    float* __restrict__ out, __half* __restrict__ outh)
{
    const int row = blockIdx.x;
    const int tid = threadIdx.x;
    const size_t off = (size_t)row * Cq + tid * 4;

    float4 v = *(const float4*)&in[off];
    float s = v.x + v.y + v.z + v.w;
    float ss = v.x * v.x + v.y * v.y + v.z * v.z + v.w * v.w;

#pragma unroll
    for (int o2 = 16; o2 > 0; o2 >>= 1) {
        s  += __shfl_xor_sync(0xffffffffu, s,  o2);
        ss += __shfl_xor_sync(0xffffffffu, ss, o2);
    }
    __shared__ float sh_s[8], sh_ss[8], red[2];
    if ((tid & 31) == 0) { sh_s[tid >> 5] = s; sh_ss[tid >> 5] = ss; }
    __syncthreads();
    if (tid < 32) {
        float a  = (tid < 8) ? sh_s[tid]  : 0.f;
        float a2 = (tid < 8) ? sh_ss[tid] : 0.f;
#pragma unroll
        for (int o2 = 4; o2 > 0; o2 >>= 1) {
            a  += __shfl_xor_sync(0xffffffffu, a,  o2);
            a2 += __shfl_xor_sync(0xffffffffu, a2, o2);
        }
        if (tid == 0) {
            float mean = a * (1.f / Cq);
            float var = a2 * (1.f / Cq) - mean * mean;
            red[0] = mean;
            red[1] = rsqrtf(var + EPSLN);
        }
    }
    __syncthreads();
    float mean = red[0], inv = red[1];

    float4 gv = *(const float4*)&g[tid * 4];
    float4 bv = *(const float4*)&bt[tid * 4];
    float4 rv = *(const float4*)&res[off];
    float4 o;
    o.x = rv.x + (v.x - mean) * inv * gv.x + bv.x;
    o.y = rv.y + (v.y - mean) * inv * gv.y + bv.y;
    o.z = rv.z + (v.z - mean) * inv * gv.z + bv.z;
    o.w = rv.w + (v.w - mean) * inv * gv.w + bv.w;
    *(float4*)&out[off] = o;
    if (outh) {
        uint2 ho;
        *(__half2*)&ho.x = __floats2half2_rn(o.x, o.y);
        *(__half2*)&ho.y = __floats2half2_rn(o.z, o.w);
        *(uint2*)&outh[off] = ho;
    }
}

// ---------------------------------------------------------------------------
// host launcher: 4 quarter-chains over origin + 3 streams (round-8 footprint)
// ---------------------------------------------------------------------------
extern "C" void kernel_launch(void* const* d_in, const int* in_sizes, int n_in,
                              void* d_out, int out_size)
{
    const float* x      = (const float*)d_in[0];
    const float* qkv_w  = (const float*)d_in[1];
    const float* qkv_b  = (const float*)d_in[2];
    const float* proj_w = (const float*)d_in[3];
    const float* proj_b = (const float*)d_in[4];
    const float* n1_g   = (const float*)d_in[5];
    const float* n1_b   = (const float*)d_in[6];
    const float* fc1_w  = (const float*)d_in[7];
    const float* fc1_b  = (const float*)d_in[8];
    const float* fc2_w  = (const float*)d_in[9];
    const float* fc2_b  = (const float*)d_in[10];
    const float* n2_g   = (const float*)d_in[11];
    const float* n2_b   = (const float*)d_in[12];
    float* out = (float*)d_out;

    static __half *p_xh = nullptr, *p_qkvh, *p_atth, *p_y1h, *p_h1h,
                  *p_wqkv, *p_wproj, *p_wfc1, *p_wfc2;
    static float *p_a, *p_y1, *p_h2;
    static cudaStream_t sW, sA, sB;
    static cudaEvent_t evStart, evRoot, evX, evW, evA, evB, evC;
    if (!p_xh) {
        cudaGetSymbolAddress((void**)&p_xh,   g_xh);
        cudaGetSymbolAddress((void**)&p_qkvh, g_qkvh);
        cudaGetSymbolAddress((void**)&p_atth, g_atth);
        cudaGetSymbolAddress((void**)&p_a,    g_a);
        cudaGetSymbolAddress((void**)&p_y1,   g_y1);
        cudaGetSymbolAddress((void**)&p_y1h,  g_y1h);
        cudaGetSymbolAddress((void**)&p_h1h,  g_h1h);
        cudaGetSymbolAddress((void**)&p_h2,   g_h2);
        cudaGetSymbolAddress((void**)&p_wqkv, g_wqkvT);
        cudaGetSymbolAddress((void**)&p_wproj, g_wprojT);
        cudaGetSymbolAddress((void**)&p_wfc1, g_wfc1T);
        cudaGetSymbolAddress((void**)&p_wfc2, g_wfc2T);
        cudaFuncSetAttribute(gemm_fp16, cudaFuncAttributeMaxDynamicSharedMemorySize, GEMM_SMEM);
        cudaFuncSetAttribute(attn_fp16, cudaFuncAttributeMaxDynamicSharedMemorySize, ATTN_SMEM);
        cudaStreamCreateWithFlags(&sW, cudaStreamNonBlocking);
        cudaStreamCreateWithFlags(&sA, cudaStreamNonBlocking);
        cudaStreamCreateWithFlags(&sB, cudaStreamNonBlocking);
        cudaEventCreateWithFlags(&evStart, cudaEventDisableTiming);
        cudaEventCreateWithFlags(&evRoot, cudaEventDisableTiming);
        cudaEventCreateWithFlags(&evX, cudaEventDisableTiming);
        cudaEventCreateWithFlags(&evW, cudaEventDisableTiming);
        cudaEventCreateWithFlags(&evA, cudaEventDisableTiming);
        cudaEventCreateWithFlags(&evB, cudaEventDisableTiming);
        cudaEventCreateWithFlags(&evC, cudaEventDisableTiming);
    }

    // ---- fork ----
    cudaEventRecord(evStart, 0);
    cudaStreamWaitEvent(sW, evStart, 0);
    cudaStreamWaitEvent(sA, evStart, 0);
    cudaStreamWaitEvent(sB, evStart, 0);

    // sW: proj/fc1/fc2 weight transposes (then hosts quarter 3)
    transpose_half<<<dim3(Cq / 32, Cq / 32), dim3(32, 8), 0, sW>>>(proj_w, p_wproj, Cq, Cq);
    transpose_half<<<dim3(4 * Cq / 32, Cq / 32), dim3(32, 8), 0, sW>>>(fc1_w, p_wfc1, Cq, 4 * Cq);
    transpose_half<<<dim3(Cq / 32, 4 * Cq / 32), dim3(32, 8), 0, sW>>>(fc2_w, p_wfc2, 4 * Cq, Cq);
    cudaEventRecord(evW, sW);

    // sA: x -> half (then hosts quarter 1)
    to_half<<<Mrows * Cq / 2048, 256, 0, sA>>>(x, p_xh);
    cudaEventRecord(evX, sA);

    // origin: qkv_w transpose (then hosts quarter 0)
    transpose_half<<<dim3(3 * Cq / 32, Cq / 32), dim3(32, 8)>>>(qkv_w, p_wqkv, Cq, 3 * Cq);
    cudaEventRecord(evRoot, 0);

    // chain streams: q0=origin, q1=sA, q2=sB, q3=sW
    cudaStream_t chain[NCHUNK] = {(cudaStream_t)0, sA, sB, sW};

    cudaStreamWaitEvent(0, evX, 0);            // q0 needs x->half (qkv_w local)
    cudaStreamWaitEvent(sA, evRoot, 0);        // q1 needs qkv_w (x->half local)
    cudaStreamWaitEvent(sB, evRoot, 0);        // q2 needs both
    cudaStreamWaitEvent(sB, evX, 0);
    cudaStreamWaitEvent(sW, evRoot, 0);        // q3 needs both (transposes local)
    cudaStreamWaitEvent(sW, evX, 0);

    for (int q = 0; q < NCHUNK; q++) {
        cudaStream_t st = chain[q];
        const size_t m = (size_t)q * MCHUNK;
        const __half* xh  = p_xh  + m * Cq;
        __half* qkvh      = p_qkvh + m * 3 * Cq;
        __half* atth      = p_atth + m * Cq;
        float*  a_        = p_a    + m * Cq;
        float*  y1_       = p_y1   + m * Cq;
        __half* y1h_      = p_y1h  + m * Cq;
        __half* h1h_      = p_h1h  + m * 4 * Cq;
        float*  h2_       = p_h2   + m * Cq;
        float*  out_      = out    + m * Cq;

        // qkv
        gemm_fp16<<<dim3(3 * Cq / 128, MCHUNK / 128), 256, GEMM_SMEM, st>>>(
            xh, p_wqkv, qkv_b, nullptr, qkvh, 3 * Cq, Cq, 0);
        // attention (2 batches x 16 heads)
        attn_fp16<<<dim3(Nq / 64, (Bq / NCHUNK) * 16), 128, ATTN_SMEM, st>>>(qkvh, atth);
        // proj (needs transposed proj_w; q3 is on sW so already ordered)
        if (st != sW) cudaStreamWaitEvent(st, evW, 0);
        gemm_fp16<<<dim3(Cq / 128, MCHUNK / 128), 256, GEMM_SMEM, st>>>(
            atth, p_wproj, proj_b, a_, nullptr, Cq, Cq, 0);
        // y1 = a + LN(a)
        ln_add_kernel<<<MCHUNK, 256, 0, st>>>(a_, a_, n1_g, n1_b, y1_, y1h_);
        // fc1
        gemm_fp16<<<dim3(4 * Cq / 128, MCHUNK / 128), 256, GEMM_SMEM, st>>>(
            y1h_, p_wfc1, fc1_b, nullptr, h1h_, 4 * Cq, Cq, 1);
        // fc2
        gemm_fp16<<<dim3(Cq / 128, MCHUNK / 128), 256, GEMM_SMEM, st>>>(
            h1h_, p_wfc2, fc2_b, h2_, nullptr, Cq, 4 * Cq, 0);
        // out = y1 + LN(h2)
        ln_add_kernel<<<MCHUNK, 256, 0, st>>>(h2_, y1_, n2_g, n2_b, out_, nullptr);
    }

    // ---- join non-origin chains back to origin ----
    cudaEventRecord(evA, sA);
    cudaEventRecord(evB, sB);
    cudaEventRecord(evC, sW);
    cudaStreamWaitEvent(0, evA, 0);
    cudaStreamWaitEvent(0, evB, 0);
    cudaStreamWaitEvent(0, evC, 0);
}

// round 14
// speedup vs baseline: 1.1676x; 1.1178x over previous
#include <cuda_runtime.h>
#include <cuda_fp16.h>
#include <math.h>
#include <stdint.h>

// ---------------------------------------------------------------------------
// ViT block, all matmul on mma.sync fp16 (fp32 accumulate).
// Four batch-quarters pipelined across origin + 3 created streams.
// GEMM: BK=64, 3-stage cp.async ring (halved barrier count vs BK=32/4-stage).
// ---------------------------------------------------------------------------

#define Bq   8
#define Nq   1024
#define Cq   1024
#define Mrows (Bq*Nq)          // 8192
#define NCHUNK 4
#define MCHUNK (Mrows/NCHUNK)  // 2048 rows (2 batches) per chain
#define EPSLN 1e-6f

// Scratch (static device memory)
__device__ __half g_xh  [Mrows * Cq];
__device__ __half g_qkvh[Mrows * 3 * Cq];
__device__ __half g_atth[Mrows * Cq];
__device__ float  g_a   [Mrows * Cq];
__device__ float  g_y1  [Mrows * Cq];
__device__ __half g_y1h [Mrows * Cq];
__device__ __half g_h1h [Mrows * 4 * Cq];
__device__ float  g_h2  [Mrows * Cq];
__device__ __half g_wqkvT[3 * Cq * Cq];
__device__ __half g_wprojT[Cq * Cq];
__device__ __half g_wfc1T[4 * Cq * Cq];
__device__ __half g_wfc2T[Cq * 4 * Cq];

__device__ __forceinline__ uint32_t smem_u32(const void* p) {
    uint32_t a;
    asm("{ .reg .u64 t; cvta.to.shared.u64 t, %1; cvt.u32.u64 %0, t; }" : "=r"(a) : "l"(p));
    return a;
}

#define MMA_F16(d, a, b)                                                   \
    asm volatile(                                                          \
        "mma.sync.aligned.m16n8k16.row.col.f32.f16.f16.f32 "               \
        "{%0,%1,%2,%3}, {%4,%5,%6,%7}, {%8,%9}, {%0,%1,%2,%3};"            \
        : "+f"(d[0]), "+f"(d[1]), "+f"(d[2]), "+f"(d[3])                   \
        : "r"(a[0]), "r"(a[1]), "r"(a[2]), "r"(a[3]), "r"(b[0]), "r"(b[1]))

#define LDSM_X4(r0, r1, r2, r3, addr)                                      \
    asm volatile("ldmatrix.sync.aligned.m8n8.x4.shared.b16 {%0,%1,%2,%3}, [%4];" \
                 : "=r"(r0), "=r"(r1), "=r"(r2), "=r"(r3) : "r"(addr))

#define CP_ASYNC16(dst, src) \
    asm volatile("cp.async.cg.shared.global [%0], [%1], 16;" :: "r"(dst), "l"(src))
#define CP_COMMIT() asm volatile("cp.async.commit_group;" ::: "memory")
#define CP_WAIT(n)  asm volatile("cp.async.wait_group %0;" :: "n"(n) : "memory")

extern __shared__ __align__(16) char g_dynsmem[];

// ---------------------------------------------------------------------------
// fp16 mma GEMM: C[M,N] = A[M,K] @ Bt[N,K]^T + bias (+GELU).
// 128x128 tile, BK=64, 3-stage cp.async, 256 threads (8 warps, 64x32 tiles).
// Stage: A 128 rows x 72 halves (144 B/row) + B same = 36864 B. 3 stages.
// Fragments via ldmatrix.x4 (36-word row stride: banks 4r mod 32, no conflict).
// ---------------------------------------------------------------------------
#define GSTG 36864
#define GEMM_SMEM (3 * GSTG)   // 110592 B; 2 CTAs/SM = 221184 <= 228KB

__global__ __launch_bounds__(256, 2) void gemm_fp16(
    const __half* __restrict__ A, const __half* __restrict__ Bt,
    const float* __restrict__ bias, float* __restrict__ Cf,
    __half* __restrict__ Ch, int N, int K, int gelu)
{
    const uint32_t smu = smem_u32(g_dynsmem);

    const int tid  = threadIdx.x;
    const int lane = tid & 31;
    const int warp = tid >> 5;
    const int gid  = lane >> 2;
    const int tig  = lane & 3;
    const int wm   = (warp >> 2) * 64;
    const int wn   = (warp & 3) * 32;
    const int bm   = blockIdx.y * 128;
    const int bn   = blockIdx.x * 128;

    // ldmatrix per-lane address components (bytes, within stage; 72h rows)
    const int lrowA = ((lane >> 3) & 1) * 8 + (lane & 7);
    const int lcolA = (lane >> 4) * 8;
    const int lrowB = ((lane >> 4) & 1) * 8 + (lane & 7);
    const int lcolB = ((lane >> 3) & 1) * 8;
    const uint32_t aoff = (uint32_t)(((wm + lrowA) * 72 + lcolA) * 2);
    const uint32_t boff = (uint32_t)(GSTG / 2 + ((wn + lrowB) * 72 + lcolB) * 2);

    float acc[4][4][4];
#pragma unroll
    for (int mt = 0; mt < 4; mt++)
#pragma unroll
        for (int nt = 0; nt < 4; nt++)
#pragma unroll
            for (int r = 0; r < 4; r++) acc[mt][nt][r] = 0.f;

    const int T = K >> 6;   // BK=64 tiles

    // copy coords: 4 chunks of 16B per tensor per thread (128 rows x 8 chunks)
#define GEMM_ISSUE(t)                                                            \
    do {                                                                         \
        const uint32_t sb_ = smu + (uint32_t)(((t) % 3) * GSTG);                 \
        _Pragma("unroll")                                                        \
        for (int i_ = 0; i_ < 4; i_++) {                                         \
            const int idx_ = tid + i_ * 256;                                     \
            const int r_ = idx_ >> 3;                                            \
            const int c8_ = idx_ & 7;                                            \
            CP_ASYNC16(sb_ + (uint32_t)(r_ * 144 + c8_ * 16),                    \
                       &A[(size_t)(bm + r_) * K + (t) * 64 + c8_ * 8]);          \
            CP_ASYNC16(sb_ + (uint32_t)(GSTG / 2 + r_ * 144 + c8_ * 16),         \
                       &Bt[(size_t)(bn + r_) * K + (t) * 64 + c8_ * 8]);         \
        }                                                                        \
        CP_COMMIT();                                                             \
    } while (0)

    GEMM_ISSUE(0); GEMM_ISSUE(1);

    for (int t = 0; t < T; t++) {
        if (t < T - 1) { CP_WAIT(1); }
        else           { CP_WAIT(0); }
        __syncthreads();
        if (t + 2 < T) GEMM_ISSUE(t + 2);

        const uint32_t sb = smu + (uint32_t)((t % 3) * GSTG);
#pragma unroll
        for (int ks = 0; ks < 4; ks++) {          // 4 k-steps of 16
            uint32_t afr[4][4], bfr[4][2];
#pragma unroll
            for (int mt = 0; mt < 4; mt++)
                LDSM_X4(afr[mt][0], afr[mt][1], afr[mt][2], afr[mt][3],
                        sb + aoff + (uint32_t)(mt * 2304 + ks * 32));
#pragma unroll
            for (int ntp = 0; ntp < 2; ntp++)
                LDSM_X4(bfr[2 * ntp][0], bfr[2 * ntp][1],
                        bfr[2 * ntp + 1][0], bfr[2 * ntp + 1][1],
                        sb + boff + (uint32_t)(ntp * 2304 + ks * 32));
#pragma unroll
            for (int mt = 0; mt < 4; mt++)
#pragma unroll
                for (int nt = 0; nt < 4; nt++)
                    MMA_F16(acc[mt][nt], afr[mt], bfr[nt]);
        }
    }
#undef GEMM_ISSUE

#pragma unroll
    for (int mt = 0; mt < 4; mt++) {
        const int row0 = bm + wm + mt * 16 + gid;
#pragma unroll
        for (int nt = 0; nt < 4; nt++) {
            const int col = bn + wn + nt * 8 + tig * 2;
            float2 bv = *(const float2*)&bias[col];
            float c0 = acc[mt][nt][0] + bv.x;
            float c1 = acc[mt][nt][1] + bv.y;
            float c2 = acc[mt][nt][2] + bv.x;
            float c3 = acc[mt][nt][3] + bv.y;
            if (gelu) {
                c0 = 0.5f * c0 * (1.f + erff(c0 * 0.70710678118654752f));
                c1 = 0.5f * c1 * (1.f + erff(c1 * 0.70710678118654752f));
                c2 = 0.5f * c2 * (1.f + erff(c2 * 0.70710678118654752f));
                c3 = 0.5f * c3 * (1.f + erff(c3 * 0.70710678118654752f));
            }
            if (Cf) {
                float2 o01; o01.x = c0; o01.y = c1;
                float2 o23; o23.x = c2; o23.y = c3;
                *(float2*)&Cf[(size_t)row0 * N + col] = o01;
                *(float2*)&Cf[(size_t)(row0 + 8) * N + col] = o23;
            }
            if (Ch) {
                *(__half2*)&Ch[(size_t)row0 * N + col] = __floats2half2_rn(c0, c1);
                *(__half2*)&Ch[(size_t)(row0 + 8) * N + col] = __floats2half2_rn(c2, c3);
            }
        }
    }
}

// ---------------------------------------------------------------------------
// Flash attention, fp16 mma, cp.async double-buffered K/V, ldmatrix frags.
// grid (Nq/64, nbatch*H), 128 threads (4 warps, 16 q-rows each).
// ---------------------------------------------------------------------------
#define AS_H 72
#define ATTN_SMEM (5 * 64 * AS_H * 2)

__global__ __launch_bounds__(128, 4) void attn_fp16(
    const __half* __restrict__ qkv, __half* __restrict__ out)
{
    __half* Qs = (__half*)g_dynsmem;
    const uint32_t qbase = smem_u32(Qs);
    const uint32_t kbase0 = qbase + 64 * AS_H * 2;
    const uint32_t vbase0 = qbase + 3 * 64 * AS_H * 2;

    const int bh = blockIdx.y;
    const int b = bh >> 4;
    const int h = bh & 15;
    const int q0 = blockIdx.x * 64;
    const int tid = threadIdx.x;
    const int wid = tid >> 5;
    const int lane = tid & 31;
    const int gid = lane >> 2;
    const int tig = lane & 3;
    const int row0 = wid * 16 + gid;

    const size_t base = (size_t)b * Nq * (3 * Cq);
    const __half2 sc2 = __float2half2_rn(0.125f);

    const int lrowA = ((lane >> 3) & 1) * 8 + (lane & 7);
    const int lcolA = (lane >> 4) * 8;
    const int lrowB = ((lane >> 4) & 1) * 8 + (lane & 7);
    const int lcolB = ((lane >> 3) & 1) * 8;
    const uint32_t qoff = (uint32_t)(((wid * 16 + lrowA) * AS_H + lcolA) * 2);
    const uint32_t koff = (uint32_t)((lrowB * AS_H + lcolB) * 2);

    const int cr = tid >> 3;
    const int cc8 = tid & 7;

#pragma unroll
    for (int i = 0; i < 4; i++) {
        int idx = tid + i * 128;
        int r = idx >> 3;
        int c8 = idx & 7;
        uint4 v = *(const uint4*)&qkv[base + (size_t)(q0 + r) * (3 * Cq) + h * 64 + c8 * 8];
        __half2* hv = (__half2*)&v;
        hv[0] = __hmul2(hv[0], sc2);
        hv[1] = __hmul2(hv[1], sc2);
        hv[2] = __hmul2(hv[2], sc2);
        hv[3] = __hmul2(hv[3], sc2);
        *(uint4*)&Qs[r * AS_H + c8 * 8] = v;
    }

#define ATTN_ISSUE(t)                                                            \
    do {                                                                         \
        const uint32_t kb_ = kbase0 + (uint32_t)(((t) & 1) * 64 * AS_H * 2);     \
        const uint32_t vb_ = vbase0 + (uint32_t)(((t) & 1) * 64 * AS_H * 2);     \
        _Pragma("unroll")                                                        \
        for (int i_ = 0; i_ < 4; i_++) {                                         \
            const int r_ = cr + i_ * 16;                                         \
            const size_t src_ = base + (size_t)((t) * 64 + r_) * (3 * Cq) + h * 64 + cc8 * 8; \
            CP_ASYNC16(kb_ + (r_ * AS_H + cc8 * 8) * 2, &qkv[src_ + Cq]);        \
            CP_ASYNC16(vb_ + (r_ * AS_H + cc8 * 8) * 2, &qkv[src_ + 2 * Cq]);    \
        }                                                                        \
        CP_COMMIT();                                                             \
    } while (0)

    ATTN_ISSUE(0);
    __syncthreads();

    uint32_t qf[4][4];
#pragma unroll
    for (int ks = 0; ks < 4; ks++)
        LDSM_X4(qf[ks][0], qf[ks][1], qf[ks][2], qf[ks][3], qbase + qoff + ks * 32);

    float of[8][4];
#pragma unroll
    for (int nt = 0; nt < 8; nt++)
#pragma unroll
        for (int r = 0; r < 4; r++) of[nt][r] = 0.f;
    float m0 = -INFINITY, m1 = -INFINITY, l0 = 0.f, l1 = 0.f;

    const int TT = Nq / 64;
    for (int t = 0; t < TT; t++) {
        CP_WAIT(0);
        __syncthreads();
        if (t + 1 < TT) ATTN_ISSUE(t + 1);

        const uint32_t kb = kbase0 + (uint32_t)((t & 1) * 64 * AS_H * 2);
        const uint32_t vb = vbase0 + (uint32_t)((t & 1) * 64 * AS_H * 2);

        float sf[8][4];
#pragma unroll
        for (int nt = 0; nt < 8; nt++)
#pragma unroll
            for (int r = 0; r < 4; r++) sf[nt][r] = 0.f;
#pragma unroll
        for (int ks = 0; ks < 4; ks++) {
#pragma unroll
            for (int ntp = 0; ntp < 4; ntp++) {
                uint32_t b0, b1, b2, b3;
                LDSM_X4(b0, b1, b2, b3, kb + koff + (uint32_t)(ntp * 16 * AS_H * 2 + ks * 32));
                uint32_t f0[2] = {b0, b1};
                uint32_t f1[2] = {b2, b3};
                MMA_F16(sf[2 * ntp], qf[ks], f0);
                MMA_F16(sf[2 * ntp + 1], qf[ks], f1);
            }
        }

        float mx0 = -INFINITY, mx1 = -INFINITY;
#pragma unroll
        for (int nt = 0; nt < 8; nt++) {
            mx0 = fmaxf(mx0, fmaxf(sf[nt][0], sf[nt][1]));
            mx1 = fmaxf(mx1, fmaxf(sf[nt][2], sf[nt][3]));
        }
        mx0 = fmaxf(mx0, __shfl_xor_sync(0xffffffffu, mx0, 1));
        mx0 = fmaxf(mx0, __shfl_xor_sync(0xffffffffu, mx0, 2));
        mx1 = fmaxf(mx1, __shfl_xor_sync(0xffffffffu, mx1, 1));
        mx1 = fmaxf(mx1, __shfl_xor_sync(0xffffffffu, mx1, 2));
        const float mn0 = fmaxf(m0, mx0);
        const float mn1 = fmaxf(m1, mx1);
        const float cr0 = __expf(m0 - mn0);
        const float cr1 = __expf(m1 - mn1);
        float rs0 = 0.f, rs1 = 0.f;
#pragma unroll
        for (int nt = 0; nt < 8; nt++) {
            float p0 = __expf(sf[nt][0] - mn0);
            float p1 = __expf(sf[nt][1] - mn0);
            float p2 = __expf(sf[nt][2] - mn1);
            float p3 = __expf(sf[nt][3] - mn1);
            rs0 += p0 + p1;
            rs1 += p2 + p3;
            *(__half2*)&Qs[row0 * AS_H + nt * 8 + tig * 2] = __floats2half2_rn(p0, p1);
            *(__half2*)&Qs[(row0 + 8) * AS_H + nt * 8 + tig * 2] = __floats2half2_rn(p2, p3);
            of[nt][0] *= cr0; of[nt][1] *= cr0;
            of[nt][2] *= cr1; of[nt][3] *= cr1;
        }
        rs0 += __shfl_xor_sync(0xffffffffu, rs0, 1);
        rs0 += __shfl_xor_sync(0xffffffffu, rs0, 2);
        rs1 += __shfl_xor_sync(0xffffffffu, rs1, 1);
        rs1 += __shfl_xor_sync(0xffffffffu, rs1, 2);
        m0 = mn0; m1 = mn1;
        l0 = l0 * cr0 + rs0;
        l1 = l1 * cr1 + rs1;
        __syncwarp();

        const int rl = lane & 15;
#pragma unroll
        for (int ks = 0; ks < 4; ks++) {
            uint32_t pf[4];
            LDSM_X4(pf[0], pf[1], pf[2], pf[3], qbase + qoff + (uint32_t)(ks * 32));
#pragma unroll
            for (int nt = 0; nt < 8; nt++) {
                uint32_t b0, b1;
                uint32_t addr = vb + (uint32_t)(((ks * 16 + rl) * AS_H + nt * 8) * 2);
                asm volatile(
                    "ldmatrix.sync.aligned.m8n8.x2.trans.shared.b16 {%0,%1}, [%2];"
                    : "=r"(b0), "=r"(b1) : "r"(addr));
                uint32_t bfr[2] = {b0, b1};
                MMA_F16(of[nt], pf, bfr);
            }
        }
        __syncwarp();
    }
#undef ATTN_ISSUE

    const float inv0 = 1.f / l0;
    const float inv1 = 1.f / l1;
    const size_t grow0 = (size_t)b * Nq + q0 + row0;
#pragma unroll
    for (int nt = 0; nt < 8; nt++) {
        const int col = h * 64 + nt * 8 + tig * 2;
        *(__half2*)&out[grow0 * Cq + col] =
            __floats2half2_rn(of[nt][0] * inv0, of[nt][1] * inv0);
        *(__half2*)&out[(grow0 + 8) * Cq + col] =
            __floats2half2_rn(of[nt][2] * inv1, of[nt][3] * inv1);
    }
}

// ---------------------------------------------------------------------------
// fp32 -> half copy (8 elems/thread)
// ---------------------------------------------------------------------------
__global__ __launch_bounds__(256) void to_half(
    const float* __restrict__ in, __half* __restrict__ out)
{
    const size_t i = ((size_t)blockIdx.x * 256 + threadIdx.x) * 8;
    float4 v0 = *(const float4*)&in[i];
    float4 v1 = *(const float4*)&in[i + 4];
    uint4 o;
    *(__half2*)&o.x = __floats2half2_rn(v0.x, v0.y);
    *(__half2*)&o.y = __floats2half2_rn(v0.z, v0.w);
    *(__half2*)&o.z = __floats2half2_rn(v1.x, v1.y);
    *(__half2*)&o.w = __floats2half2_rn(v1.z, v1.w);
    *(uint4*)&out[i] = o;
}

// ---------------------------------------------------------------------------
// transpose + fp16 convert: out[n][k] = half(in[k][n])
// ---------------------------------------------------------------------------
__global__ __launch_bounds__(256) void transpose_half(
    const float* __restrict__ in, __half* __restrict__ out, int K, int N)
{
    __shared__ float t[32][33];
    const int n0 = blockIdx.x * 32, k0 = blockIdx.y * 32;
    const int tx = threadIdx.x, ty = threadIdx.y;
#pragma unroll
    for (int i = 0; i < 4; i++)
        t[ty + i * 8][tx] = in[(size_t)(k0 + ty + i * 8) * N + n0 + tx];
    __syncthreads();
#pragma unroll
    for (int i = 0; i < 4; i++)
        out[(size_t)(n0 + ty + i * 8) * K + k0 + tx] = __float2half_rn(t[tx][ty + i * 8]);
}

// ---------------------------------------------------------------------------
// out = res + LayerNorm(in)*g + b ; optional half copy of out
// ---------------------------------------------------------------------------
__global__ __launch_bounds__(256) void ln_add_kernel(
    const float* __restrict__ in, const float* __restrict__ res,
    const float* __restrict__ g, const float* __restrict__ bt,
    float* __restrict__ out, __half* __restrict__ outh)
{
    const int row = blockIdx.x;
    const int tid = threadIdx.x;
    const size_t off = (size_t)row * Cq + tid * 4;

    float4 v = *(const float4*)&in[off];
    float s = v.x + v.y + v.z + v.w;
    float ss = v.x * v.x + v.y * v.y + v.z * v.z + v.w * v.w;

#pragma unroll
    for (int o2 = 16; o2 > 0; o2 >>= 1) {
        s  += __shfl_xor_sync(0xffffffffu, s,  o2);
        ss += __shfl_xor_sync(0xffffffffu, ss, o2);
    }
    __shared__ float sh_s[8], sh_ss[8], red[2];
    if ((tid & 31) == 0) { sh_s[tid >> 5] = s; sh_ss[tid >> 5] = ss; }
    __syncthreads();
    if (tid < 32) {
        float a  = (tid < 8) ? sh_s[tid]  : 0.f;
        float a2 = (tid < 8) ? sh_ss[tid] : 0.f;
#pragma unroll
        for (int o2 = 4; o2 > 0; o2 >>= 1) {
            a  += __shfl_xor_sync(0xffffffffu, a,  o2);
            a2 += __shfl_xor_sync(0xffffffffu, a2, o2);
        }
        if (tid == 0) {
            float mean = a * (1.f / Cq);
            float var = a2 * (1.f / Cq) - mean * mean;
            red[0] = mean;
            red[1] = rsqrtf(var + EPSLN);
        }
    }
    __syncthreads();
    float mean = red[0], inv = red[1];

    float4 gv = *(const float4*)&g[tid * 4];
    float4 bv = *(const float4*)&bt[tid * 4];
    float4 rv = *(const float4*)&res[off];
    float4 o;
    o.x = rv.x + (v.x - mean) * inv * gv.x + bv.x;
    o.y = rv.y + (v.y - mean) * inv * gv.y + bv.y;
    o.z = rv.z + (v.z - mean) * inv * gv.z + bv.z;
    o.w = rv.w + (v.w - mean) * inv * gv.w + bv.w;
    *(float4*)&out[off] = o;
    if (outh) {
        uint2 ho;
        *(__half2*)&ho.x = __floats2half2_rn(o.x, o.y);
        *(__half2*)&ho.y = __floats2half2_rn(o.z, o.w);
        *(uint2*)&outh[off] = ho;
    }
}

// ---------------------------------------------------------------------------
// host launcher: 4 quarter-chains over origin + 3 streams (round-8 footprint)
// ---------------------------------------------------------------------------
extern "C" void kernel_launch(void* const* d_in, const int* in_sizes, int n_in,
                              void* d_out, int out_size)
{
    const float* x      = (const float*)d_in[0];
    const float* qkv_w  = (const float*)d_in[1];
    const float* qkv_b  = (const float*)d_in[2];
    const float* proj_w = (const float*)d_in[3];
    const float* proj_b = (const float*)d_in[4];
    const float* n1_g   = (const float*)d_in[5];
    const float* n1_b   = (const float*)d_in[6];
    const float* fc1_w  = (const float*)d_in[7];
    const float* fc1_b  = (const float*)d_in[8];
    const float* fc2_w  = (const float*)d_in[9];
    const float* fc2_b  = (const float*)d_in[10];
    const float* n2_g   = (const float*)d_in[11];
    const float* n2_b   = (const float*)d_in[12];
    float* out = (float*)d_out;

    static __half *p_xh = nullptr, *p_qkvh, *p_atth, *p_y1h, *p_h1h,
                  *p_wqkv, *p_wproj, *p_wfc1, *p_wfc2;
    static float *p_a, *p_y1, *p_h2;
    static cudaStream_t sW, sA, sB;
    static cudaEvent_t evStart, evRoot, evX, evW, evA, evB, evC;
    if (!p_xh) {
        cudaGetSymbolAddress((void**)&p_xh,   g_xh);
        cudaGetSymbolAddress((void**)&p_qkvh, g_qkvh);
        cudaGetSymbolAddress((void**)&p_atth, g_atth);
        cudaGetSymbolAddress((void**)&p_a,    g_a);
        cudaGetSymbolAddress((void**)&p_y1,   g_y1);
        cudaGetSymbolAddress((void**)&p_y1h,  g_y1h);
        cudaGetSymbolAddress((void**)&p_h1h,  g_h1h);
        cudaGetSymbolAddress((void**)&p_h2,   g_h2);
        cudaGetSymbolAddress((void**)&p_wqkv, g_wqkvT);
        cudaGetSymbolAddress((void**)&p_wproj, g_wprojT);
        cudaGetSymbolAddress((void**)&p_wfc1, g_wfc1T);
        cudaGetSymbolAddress((void**)&p_wfc2, g_wfc2T);
        cudaFuncSetAttribute(gemm_fp16, cudaFuncAttributeMaxDynamicSharedMemorySize, GEMM_SMEM);
        cudaFuncSetAttribute(attn_fp16, cudaFuncAttributeMaxDynamicSharedMemorySize, ATTN_SMEM);
        cudaStreamCreateWithFlags(&sW, cudaStreamNonBlocking);
        cudaStreamCreateWithFlags(&sA, cudaStreamNonBlocking);
        cudaStreamCreateWithFlags(&sB, cudaStreamNonBlocking);
        cudaEventCreateWithFlags(&evStart, cudaEventDisableTiming);
        cudaEventCreateWithFlags(&evRoot, cudaEventDisableTiming);
        cudaEventCreateWithFlags(&evX, cudaEventDisableTiming);
        cudaEventCreateWithFlags(&evW, cudaEventDisableTiming);
        cudaEventCreateWithFlags(&evA, cudaEventDisableTiming);
        cudaEventCreateWithFlags(&evB, cudaEventDisableTiming);
        cudaEventCreateWithFlags(&evC, cudaEventDisableTiming);
    }

    // ---- fork ----
    cudaEventRecord(evStart, 0);
    cudaStreamWaitEvent(sW, evStart, 0);
    cudaStreamWaitEvent(sA, evStart, 0);
    cudaStreamWaitEvent(sB, evStart, 0);

    // sW: proj/fc1/fc2 weight transposes (then hosts quarter 3)
    transpose_half<<<dim3(Cq / 32, Cq / 32), dim3(32, 8), 0, sW>>>(proj_w, p_wproj, Cq, Cq);
    transpose_half<<<dim3(4 * Cq / 32, Cq / 32), dim3(32, 8), 0, sW>>>(fc1_w, p_wfc1, Cq, 4 * Cq);
    transpose_half<<<dim3(Cq / 32, 4 * Cq / 32), dim3(32, 8), 0, sW>>>(fc2_w, p_wfc2, 4 * Cq, Cq);
    cudaEventRecord(evW, sW);

    // sA: x -> half (then hosts quarter 1)
    to_half<<<Mrows * Cq / 2048, 256, 0, sA>>>(x, p_xh);
    cudaEventRecord(evX, sA);

    // origin: qkv_w transpose (then hosts quarter 0)
    transpose_half<<<dim3(3 * Cq / 32, Cq / 32), dim3(32, 8)>>>(qkv_w, p_wqkv, Cq, 3 * Cq);
    cudaEventRecord(evRoot, 0);

    // chain streams: q0=origin, q1=sA, q2=sB, q3=sW
    cudaStream_t chain[NCHUNK] = {(cudaStream_t)0, sA, sB, sW};

    cudaStreamWaitEvent(0, evX, 0);            // q0 needs x->half (qkv_w local)
    cudaStreamWaitEvent(sA, evRoot, 0);        // q1 needs qkv_w (x->half local)
    cudaStreamWaitEvent(sB, evRoot, 0);        // q2 needs both
    cudaStreamWaitEvent(sB, evX, 0);
    cudaStreamWaitEvent(sW, evRoot, 0);        // q3 needs both (transposes local)
    cudaStreamWaitEvent(sW, evX, 0);

    for (int q = 0; q < NCHUNK; q++) {
        cudaStream_t st = chain[q];
        const size_t m = (size_t)q * MCHUNK;
        const __half* xh  = p_xh  + m * Cq;
        __half* qkvh      = p_qkvh + m * 3 * Cq;
        __half* atth      = p_atth + m * Cq;
        float*  a_        = p_a    + m * Cq;
        float*  y1_       = p_y1   + m * Cq;
        __half* y1h_      = p_y1h  + m * Cq;
        __half* h1h_      = p_h1h  + m * 4 * Cq;
        float*  h2_       = p_h2   + m * Cq;
        float*  out_      = out    + m * Cq;

        // qkv
        gemm_fp16<<<dim3(3 * Cq / 128, MCHUNK / 128), 256, GEMM_SMEM, st>>>(
            xh, p_wqkv, qkv_b, nullptr, qkvh, 3 * Cq, Cq, 0);
        // attention (2 batches x 16 heads)
        attn_fp16<<<dim3(Nq / 64, (Bq / NCHUNK) * 16), 128, ATTN_SMEM, st>>>(qkvh, atth);
        // proj (needs transposed proj_w; q3 is on sW so already ordered)
        if (st != sW) cudaStreamWaitEvent(st, evW, 0);
        gemm_fp16<<<dim3(Cq / 128, MCHUNK / 128), 256, GEMM_SMEM, st>>>(
            atth, p_wproj, proj_b, a_, nullptr, Cq, Cq, 0);
        // y1 = a + LN(a)
        ln_add_kernel<<<MCHUNK, 256, 0, st>>>(a_, a_, n1_g, n1_b, y1_, y1h_);
        // fc1
        gemm_fp16<<<dim3(4 * Cq / 128, MCHUNK / 128), 256, GEMM_SMEM, st>>>(
            y1h_, p_wfc1, fc1_b, nullptr, h1h_, 4 * Cq, Cq, 1);
        // fc2
        gemm_fp16<<<dim3(Cq / 128, MCHUNK / 128), 256, GEMM_SMEM, st>>>(
            h1h_, p_wfc2, fc2_b, h2_, nullptr, Cq, 4 * Cq, 0);
        // out = y1 + LN(h2)
        ln_add_kernel<<<MCHUNK, 256, 0, st>>>(h2_, y1_, n2_g, n2_b, out_, nullptr);
    }

    // ---- join non-origin chains back to origin ----
    cudaEventRecord(evA, sA);
    cudaEventRecord(evB, sB);
    cudaEventRecord(evC, sW);
    cudaStreamWaitEvent(0, evA, 0);
    cudaStreamWaitEvent(0, evB, 0);
    cudaStreamWaitEvent(0, evC, 0);
}